// round 8
// baseline (speedup 1.0000x reference)
#include <cuda_runtime.h>
#include <math.h>
#include <stdint.h>

#define DIM 16
#define NA 131072
#define NB 1048576
#define NANG 2097152
#define NGRAPH 256
#define PI_F 3.14159274101257324219f   // fl32(pi)
#define CUTOFF_F 5.0f

// ---------------- scratch (static device globals; no runtime alloc) ----------
__device__ float g_h_atm[NA * DIM];
__device__ float g_h_bnd[NB * DIM];
__device__ float g_h_ang[NANG * DIM];
__device__ float g_num[NB * DIM];
__device__ float g_den[NB * DIM];
__device__ float g_table[10 * DIM];
__device__ float g_pool[NGRAPH * DIM];
__device__ int   g_mask_mode;   // 1 = mask serialized as int32, 0 = as bytes

// ---------------- XLA-style tanh (Eigen rational, f32) ------------------------
__device__ __forceinline__ float tanh_xla(float x) {
    const float kClamp = 7.90531110763549805f;
    float xc = fminf(fmaxf(x, -kClamp), kClamp);
    float s = __fmul_rn(xc, xc);
    float p = 2.00018790482477e-13f;
    p = fmaf(p, s, -8.60467152213735e-11f);
    p = fmaf(p, s, 5.12229709037114e-08f);
    p = fmaf(p, s, 1.48572235717979e-05f);
    p = fmaf(p, s, 6.37261928875436e-04f);
    p = fmaf(p, s, 4.89352455891786e-03f);
    p = __fmul_rn(xc, p);
    float q = 1.19825839466702e-06f;
    q = fmaf(q, s, 1.18534705686654e-04f);
    q = fmaf(q, s, 2.26843463243900e-03f);
    q = fmaf(q, s, 4.89352518554385e-03f);
    float r = __fdiv_rn(p, q);
    return (fabsf(x) < 0.0004f) ? x : r;
}

__device__ __forceinline__ float sigmoid_x(float x) {
    return __fadd_rn(0.5f, __fmul_rn(0.5f, tanh_xla(__fmul_rn(0.5f, x))));
}
__device__ __forceinline__ float silu_x(float x) { return __fmul_rn(x, sigmoid_x(x)); }

// ---------------- accurate exp (for gaussian basis) ---------------------------
__device__ __forceinline__ float exp_acc(float x) {
    x = fminf(fmaxf(x, -87.0f), 88.0f);
    float n = rintf(x * 1.4426950408889634f);
    float r = fmaf(-n, 0.6931457519531250f, x);
    r = fmaf(-n, 1.4286067653301945e-6f, r);
    float p = 1.3888888936737738e-3f;
    p = fmaf(p, r, 8.3333333333333333e-3f);
    p = fmaf(p, r, 4.1666666666666664e-2f);
    p = fmaf(p, r, 1.6666666666666666e-1f);
    p = fmaf(p, r, 5.0e-1f);
    p = fmaf(p, r, 1.0f);
    p = fmaf(p, r, 1.0f);
    int e = (int)n;
    float s = __int_as_float((e + 127) << 23);
    return p * s;
}

// ---------------- accurate sinf (FMA Cody-Waite, 0 <= x < ~55) ----------------
__device__ __forceinline__ float sinf_cw(float x) {
    float k = rintf(__fmul_rn(x, 0.636619772367581343f));
    float r = fmaf(k, -1.57079637050628662109375f, x);
    r = fmaf(k, 4.37113900018624283e-8f, r);
    int q = ((int)k) & 3;
    float s = __fmul_rn(r, r);
    float ps = 2.75573192239859e-6f;
    ps = fmaf(ps, s, -1.98412698412698e-4f);
    ps = fmaf(ps, s, 8.33333333333333e-3f);
    ps = fmaf(ps, s, -1.66666666666667e-1f);
    float sinr = fmaf(__fmul_rn(r, s), ps, r);
    float pc = 2.48015873015873e-5f;
    pc = fmaf(pc, s, -1.38888888888889e-3f);
    pc = fmaf(pc, s, 4.16666666666667e-2f);
    pc = fmaf(pc, s, -5.0e-1f);
    float cosr = fmaf(s, pc, 1.0f);
    float v = (q & 1) ? cosr : sinr;
    return (q & 2) ? -v : v;
}

// ---------------- misc helpers -------------------------------------------------
__device__ __forceinline__ void red_add_v4(float* p, float a, float b, float c, float d) {
    asm volatile("red.global.add.v4.f32 [%0], {%1,%2,%3,%4};"
                 :: "l"(p), "f"(a), "f"(b), "f"(c), "f"(d) : "memory");
}
__device__ __forceinline__ void load16(float* r, const float* p) {
#pragma unroll
    for (int i = 0; i < 4; i++) {
        float4 v = ((const float4*)p)[i];
        r[4 * i + 0] = v.x; r[4 * i + 1] = v.y; r[4 * i + 2] = v.z; r[4 * i + 3] = v.w;
    }
}
__device__ __forceinline__ void store16(float* p, const float* r) {
#pragma unroll
    for (int i = 0; i < 4; i++) {
        ((float4*)p)[i] = make_float4(r[4 * i + 0], r[4 * i + 1], r[4 * i + 2], r[4 * i + 3]);
    }
}

__device__ __forceinline__ void layernorm16(float* v, const float* g, const float* b) {
    float mu = 0.f;
#pragma unroll
    for (int j = 0; j < DIM; j++) mu = __fadd_rn(mu, v[j]);
    mu = __fmul_rn(mu, 0.0625f);
    float var = 0.f;
#pragma unroll
    for (int j = 0; j < DIM; j++) {
        float d0 = __fsub_rn(v[j], mu);
        var = __fadd_rn(var, __fmul_rn(d0, d0));
    }
    var = __fmul_rn(var, 0.0625f);
    float r = __frsqrt_rn(__fadd_rn(var, 1e-5f));
#pragma unroll
    for (int j = 0; j < DIM; j++) {
        float t = __fmul_rn(__fmul_rn(__fsub_rn(v[j], mu), r), g[j]);
        v[j] = __fadd_rn(t, b[j]);
    }
}

// ---------------- mask-layout detection ----------------------------------------
// If mask came from a bool array serialized as int32 (LE), every byte at offset
// i%4 != 0 in the buffer is zero. Genuine byte-bools are ~50% nonzero there.
__global__ void k_detect_mask(const unsigned char* __restrict__ m) {
    __shared__ int s_nz;
    if (threadIdx.x == 0) s_nz = 0;
    __syncthreads();
    int nz = 0;
    for (int i = threadIdx.x; i < 65536; i += blockDim.x)
        if ((i & 3) && m[i]) nz = 1;
    if (nz) atomicOr(&s_nz, 1);
    __syncthreads();
    if (threadIdx.x == 0) g_mask_mode = s_nz ? 0 : 1;
}

// ---------------- fill ---------------------------------------------------------
__global__ void k_fill0(float4* p, int n4) {
    int i = blockIdx.x * blockDim.x + threadIdx.x;
    if (i < n4) p[i] = make_float4(0.f, 0.f, 0.f, 0.f);
}

// ---------------- atom species embedding table --------------------------------
__global__ void k_atm_table(const float* __restrict__ W1, const float* __restrict__ b1,
                            const float* __restrict__ W2, const float* __restrict__ b2,
                            const float* __restrict__ lg, const float* __restrict__ lb) {
    int s = threadIdx.x;
    if (s >= 10) return;
    float h[DIM], o[DIM];
#pragma unroll
    for (int d = 0; d < DIM; d++) h[d] = silu_x(__fadd_rn(W1[s * DIM + d], b1[d]));
#pragma unroll
    for (int j = 0; j < DIM; j++) o[j] = 0.f;
#pragma unroll
    for (int k = 0; k < DIM; k++) {
        float a = h[k];
#pragma unroll
        for (int j = 0; j < DIM; j++) o[j] = fmaf(a, W2[k * DIM + j], o[j]);
    }
    float g[DIM], bb[DIM];
#pragma unroll
    for (int j = 0; j < DIM; j++) { o[j] = __fadd_rn(o[j], b2[j]); g[j] = lg[j]; bb[j] = lb[j]; }
    layernorm16(o, g, bb);
#pragma unroll
    for (int j = 0; j < DIM; j++) g_table[s * DIM + j] = o[j];
}

__global__ void k_atm_gather(const int* __restrict__ species, int n) {
    int i = blockIdx.x * blockDim.x + threadIdx.x;
    if (i >= n) return;
    int s = species[i];
    const float4* src = (const float4*)(g_table + s * DIM);
    float4* dst = (float4*)(g_h_atm + (size_t)i * DIM);
#pragma unroll
    for (int q = 0; q < 4; q++) dst[q] = src[q];
}

// ---------------- generic embed ------------------------------------------------
__device__ __forceinline__ void embed_write(const float* feat, float* out,
                                            const float* sW1, const float* sb1,
                                            const float* sW2, const float* sb2,
                                            const float* sg, const float* sb) {
    float h[DIM], o[DIM];
#pragma unroll
    for (int j = 0; j < DIM; j++) h[j] = 0.f;
#pragma unroll
    for (int k = 0; k < DIM; k++) {
        float a = feat[k];
#pragma unroll
        for (int j = 0; j < DIM; j++) h[j] = fmaf(a, sW1[k * DIM + j], h[j]);
    }
#pragma unroll
    for (int j = 0; j < DIM; j++) h[j] = silu_x(__fadd_rn(h[j], sb1[j]));
#pragma unroll
    for (int j = 0; j < DIM; j++) o[j] = 0.f;
#pragma unroll
    for (int k = 0; k < DIM; k++) {
        float a = h[k];
#pragma unroll
        for (int j = 0; j < DIM; j++) o[j] = fmaf(a, sW2[k * DIM + j], o[j]);
    }
#pragma unroll
    for (int j = 0; j < DIM; j++) o[j] = __fadd_rn(o[j], sb2[j]);
    layernorm16(o, sg, sb);
#pragma unroll
    for (int j = 0; j < DIM; j++) out[j] = o[j];
}

// ---------------- bond encoder (bessel basis) ----------------------------------
__global__ void k_enc_bnd(const float* __restrict__ xb, int n,
                          const float* __restrict__ W1, const float* __restrict__ b1,
                          const float* __restrict__ W2, const float* __restrict__ b2,
                          const float* __restrict__ lg, const float* __restrict__ lb) {
    __shared__ float sW1[256], sW2[256], sb1[16], sb2[16], sg[16], sb[16];
    int t = threadIdx.x;
    for (int i = t; i < 256; i += blockDim.x) { sW1[i] = W1[i]; sW2[i] = W2[i]; }
    if (t < 16) { sb1[t] = b1[t]; sb2[t] = b2[t]; sg[t] = lg[t]; sb[t] = lb[t]; }
    __syncthreads();
    int i = blockIdx.x * blockDim.x + t;
    if (i >= n) return;
    float xx = __fadd_rn(xb[i], 1e-5f);
    float s04 = __fsqrt_rn(0.4f);
    float feat[DIM];
#pragma unroll
    for (int j = 0; j < DIM; j++) {
        float t1 = __fmul_rn((float)(j + 1), PI_F);
        float t2 = __fmul_rn(t1, xx);
        float arg = __fdiv_rn(t2, CUTOFF_F);
        float sv = sinf_cw(arg);
        feat[j] = __fdiv_rn(__fmul_rn(s04, sv), xx);
    }
    float out[DIM];
    embed_write(feat, out, sW1, sb1, sW2, sb2, sg, sb);
    store16(g_h_bnd + (size_t)i * DIM, out);
}

// ---------------- angle encoder (gaussian basis, dual mask layout) -------------
__global__ void k_enc_ang(const float* __restrict__ xa, const unsigned char* __restrict__ mask, int n,
                          const float* __restrict__ encW1, const float* __restrict__ encb1,
                          const float* __restrict__ encW2, const float* __restrict__ encb2,
                          const float* __restrict__ encg, const float* __restrict__ encb) {
    __shared__ float sW1[2][256], sW2[2][256], sb1[2][16], sb2[2][16], sg[2][16], sb[2][16];
    int t = threadIdx.x;
    for (int i = t; i < 512; i += blockDim.x) {
        int m = i / 256, j = i % 256;
        sW1[m][j] = encW1[(2 + m) * 256 + j];
        sW2[m][j] = encW2[(2 + m) * 256 + j];
    }
    if (t < 32) {
        int m = t / 16, j = t % 16;
        sb1[m][j] = encb1[(2 + m) * 16 + j];
        sb2[m][j] = encb2[(2 + m) * 16 + j];
        sg[m][j]  = encg[(2 + m) * 16 + j];
        sb[m][j]  = encb[(2 + m) * 16 + j];
    }
    __syncthreads();
    int i = blockIdx.x * blockDim.x + t;
    if (i >= n) return;
    int mv;
    if (g_mask_mode) mv = ((const int*)mask)[i];   // bool serialized as int32
    else             mv = mask[i];                  // bool serialized as bytes
    int m = mv ? 1 : 0;
    float x = xa[i];
    float start = m ? -PI_F : 0.0f;
    float span  = m ? __fmul_rn(2.0f, PI_F) : PI_F;
    float step  = __fdiv_rn(span, 15.0f);
    float c0 = __fadd_rn(start, 0.0f);
    float c1 = __fadd_rn(start, step);
    float gamma = __fdiv_rn(1.0f, __fsub_rn(c1, c0));
    float feat[DIM];
#pragma unroll
    for (int j = 0; j < DIM; j++) {
        float cj = __fadd_rn(start, __fmul_rn((float)j, step));
        float d  = __fsub_rn(x, cj);
        float u  = __fmul_rn(gamma, d);
        float sq = __fmul_rn(u, u);
        feat[j] = exp_acc(-sq);
    }
    float out[DIM];
    embed_write(feat, out, sW1[m], sb1[m], sW2[m], sb2[m], sg[m], sb[m]);
    store16(g_h_ang + (size_t)i * DIM, out);
}

// ---------------- edge-gated conv: edge pass -----------------------------------
__global__ void k_edge(const float* __restrict__ x, float* __restrict__ e,
                       const int* __restrict__ src, const int* __restrict__ dst, int n_edges,
                       const float* __restrict__ Wall, const float* __restrict__ bvec,
                       const float* __restrict__ lng, const float* __restrict__ lnb,
                       float* __restrict__ num, float* __restrict__ den) {
    __shared__ float sW0[256], sW1[256], sW2[256], sW4[256], sb0[16], sg[16], sb[16];
    int t = threadIdx.x;
    for (int i = t; i < 256; i += blockDim.x) {
        sW0[i] = Wall[i];
        sW1[i] = Wall[256 + i];
        sW2[i] = Wall[512 + i];
        sW4[i] = Wall[1024 + i];
    }
    if (t < 16) { sb0[t] = bvec[t]; sg[t] = lng[t]; sb[t] = lnb[t]; }
    __syncthreads();
    int eid = blockIdx.x * blockDim.x + t;
    if (eid >= n_edges) return;
    int s = src[eid], d = dst[eid];
    float xs[DIM], xd[DIM], ev[DIM];
    load16(xs, x + (size_t)s * DIM);
    load16(xd, x + (size_t)d * DIM);
    load16(ev, e + (size_t)eid * DIM);
    float za[DIM], zb[DIM], zc[DIM], z[DIM];
#pragma unroll
    for (int j = 0; j < DIM; j++) { za[j] = 0.f; zb[j] = 0.f; zc[j] = 0.f; }
#pragma unroll
    for (int k = 0; k < DIM; k++) {
        float a = xs[k], b2 = xd[k], c = ev[k];
#pragma unroll
        for (int j = 0; j < DIM; j++) {
            za[j] = fmaf(a, sW0[k * DIM + j], za[j]);
            zb[j] = fmaf(b2, sW1[k * DIM + j], zb[j]);
            zc[j] = fmaf(c, sW2[k * DIM + j], zc[j]);
        }
    }
#pragma unroll
    for (int j = 0; j < DIM; j++)
        z[j] = __fadd_rn(__fadd_rn(__fadd_rn(za[j], zb[j]), zc[j]), sb0[j]);
    float sig[DIM];
#pragma unroll
    for (int j = 0; j < DIM; j++) sig[j] = sigmoid_x(z[j]);
    float* dp = den + (size_t)d * DIM;
    red_add_v4(dp + 0, sig[0], sig[1], sig[2], sig[3]);
    red_add_v4(dp + 4, sig[4], sig[5], sig[6], sig[7]);
    red_add_v4(dp + 8, sig[8], sig[9], sig[10], sig[11]);
    red_add_v4(dp + 12, sig[12], sig[13], sig[14], sig[15]);
    float msg[DIM];
#pragma unroll
    for (int j = 0; j < DIM; j++) msg[j] = 0.f;
#pragma unroll
    for (int k = 0; k < DIM; k++) {
        float a = xs[k];
#pragma unroll
        for (int j = 0; j < DIM; j++) msg[j] = fmaf(a, sW4[k * DIM + j], msg[j]);
    }
#pragma unroll
    for (int j = 0; j < DIM; j++) msg[j] = __fmul_rn(sig[j], msg[j]);
    float* np = num + (size_t)d * DIM;
    red_add_v4(np + 0, msg[0], msg[1], msg[2], msg[3]);
    red_add_v4(np + 4, msg[4], msg[5], msg[6], msg[7]);
    red_add_v4(np + 8, msg[8], msg[9], msg[10], msg[11]);
    red_add_v4(np + 12, msg[12], msg[13], msg[14], msg[15]);
    layernorm16(z, sg, sb);
#pragma unroll
    for (int j = 0; j < DIM; j++) ev[j] = __fadd_rn(ev[j], silu_x(z[j]));
    store16(e + (size_t)eid * DIM, ev);
}

// ---------------- edge-gated conv: node pass -----------------------------------
__global__ void k_node(float* __restrict__ x, int n_nodes,
                       const float* __restrict__ W3, const float* __restrict__ b1,
                       const float* __restrict__ lng, const float* __restrict__ lnb,
                       const float* __restrict__ num, const float* __restrict__ den) {
    __shared__ float sW3[256], sb1[16], sg[16], sb[16];
    int t = threadIdx.x;
    for (int i = t; i < 256; i += blockDim.x) sW3[i] = W3[i];
    if (t < 16) { sb1[t] = b1[t]; sg[t] = lng[t]; sb[t] = lnb[t]; }
    __syncthreads();
    int i = blockIdx.x * blockDim.x + t;
    if (i >= n_nodes) return;
    float xv[DIM], h[DIM], nv[DIM], dv[DIM];
    load16(xv, x + (size_t)i * DIM);
    load16(nv, num + (size_t)i * DIM);
    load16(dv, den + (size_t)i * DIM);
#pragma unroll
    for (int j = 0; j < DIM; j++) h[j] = 0.f;
#pragma unroll
    for (int k = 0; k < DIM; k++) {
        float a = xv[k];
#pragma unroll
        for (int j = 0; j < DIM; j++) h[j] = fmaf(a, sW3[k * DIM + j], h[j]);
    }
#pragma unroll
    for (int j = 0; j < DIM; j++) {
        float q = __fdiv_rn(nv[j], __fadd_rn(dv[j], 1e-5f));
        h[j] = __fadd_rn(__fadd_rn(h[j], sb1[j]), q);
    }
    layernorm16(h, sg, sb);
#pragma unroll
    for (int j = 0; j < DIM; j++) xv[j] = __fadd_rn(xv[j], silu_x(h[j]));
    store16(x + (size_t)i * DIM, xv);
}

// ---------------- pooling + head -----------------------------------------------
__global__ void k_pool(const int* __restrict__ batch, int n) {
    int i = blockIdx.x * blockDim.x + threadIdx.x;
    if (i >= n) return;
    int g = batch[i];
    float h[DIM];
    load16(h, g_h_atm + (size_t)i * DIM);
    float* p = g_pool + g * DIM;
    red_add_v4(p + 0, h[0], h[1], h[2], h[3]);
    red_add_v4(p + 4, h[4], h[5], h[6], h[7]);
    red_add_v4(p + 8, h[8], h[9], h[10], h[11]);
    red_add_v4(p + 12, h[12], h[13], h[14], h[15]);
}

__global__ void k_head(const float* __restrict__ fp,
                       const float* __restrict__ l1W, const float* __restrict__ l1b,
                       const float* __restrict__ l2W, const float* __restrict__ l2b,
                       float* __restrict__ out) {
    __shared__ float sW[288], sb1h[16], sW2h[16];
    int t = threadIdx.x;
    for (int i = t; i < 288; i += blockDim.x) sW[i] = l1W[i];
    if (t < 16) { sb1h[t] = l1b[t]; sW2h[t] = l2W[t]; }
    __syncthreads();
    int g = t;  // blockDim = 256 = NGRAPH
    float xin[18];
#pragma unroll
    for (int j = 0; j < DIM; j++) xin[j] = g_pool[g * DIM + j];
    xin[16] = fp[2 * g];
    xin[17] = fp[2 * g + 1];
    float acc = 0.f;
#pragma unroll
    for (int d = 0; d < DIM; d++) {
        float tv = 0.f;
#pragma unroll
        for (int j = 0; j < 18; j++) tv = fmaf(xin[j], sW[j * DIM + d], tv);
        tv = __fadd_rn(tv, sb1h[d]);
        tv = (tv >= 0.f) ? tv : __fmul_rn(0.01f, tv);
        acc = fmaf(tv, sW2h[d], acc);
    }
    out[g] = __fadd_rn(acc, l2b[0]);
}

// ---------------- host ----------------------------------------------------------
extern "C" void kernel_launch(void* const* d_in, const int* in_sizes, int n_in,
                              void* d_out, int out_size) {
    const int* x_atm            = (const int*)d_in[0];
    const float* x_bnd          = (const float*)d_in[1];
    const float* x_ang          = (const float*)d_in[2];
    const unsigned char* mask   = (const unsigned char*)d_in[3];
    const int* eG               = (const int*)d_in[4];
    const int* eA               = (const int*)d_in[5];
    const int* batch            = (const int*)d_in[6];
    const float* fp             = (const float*)d_in[7];
    const float* enc_W1         = (const float*)d_in[8];
    const float* enc_b1         = (const float*)d_in[9];
    const float* enc_W2         = (const float*)d_in[10];
    const float* enc_b2         = (const float*)d_in[11];
    const float* enc_g          = (const float*)d_in[12];
    const float* enc_bb         = (const float*)d_in[13];
    const float* conv_W         = (const float*)d_in[14];
    const float* conv_b         = (const float*)d_in[15];
    const float* conv_ln        = (const float*)d_in[16];
    const float* l1W            = (const float*)d_in[17];
    const float* l1b            = (const float*)d_in[18];
    const float* l2W            = (const float*)d_in[19];
    const float* l2b            = (const float*)d_in[20];
    float* out = (float*)d_out;

    float *h_atm, *h_bnd, *h_ang, *num, *den, *pool;
    cudaGetSymbolAddress((void**)&h_atm, g_h_atm);
    cudaGetSymbolAddress((void**)&h_bnd, g_h_bnd);
    cudaGetSymbolAddress((void**)&h_ang, g_h_ang);
    cudaGetSymbolAddress((void**)&num, g_num);
    cudaGetSymbolAddress((void**)&den, g_den);
    cudaGetSymbolAddress((void**)&pool, g_pool);

    const int B = 256;

    // ---- mask layout detection + encoder ----
    k_detect_mask<<<1, 256>>>(mask);
    k_atm_table<<<1, 32>>>(enc_W1, enc_b1, enc_W2, enc_b2, enc_g, enc_bb);
    k_atm_gather<<<NA / B, B>>>(x_atm, NA);
    k_enc_bnd<<<NB / B, B>>>(x_bnd, NB, enc_W1 + 256, enc_b1 + 16, enc_W2 + 256,
                             enc_b2 + 16, enc_g + 16, enc_bb + 16);
    k_enc_ang<<<NANG / B, B>>>(x_ang, mask, NANG, enc_W1, enc_b1, enc_W2, enc_b2, enc_g, enc_bb);

    // ---- processor: 3 x (A conv then G conv) ----
    for (int c = 0; c < 3; c++) {
        {
            const float* Wb  = conv_W + (c * 2 + 0) * 5 * 256;
            const float* bb  = conv_b + (c * 2 + 0) * 32;
            const float* lnb_ = conv_ln + (c * 2 + 0) * 64;
            int n4 = NB * DIM / 4;
            k_fill0<<<(n4 + B - 1) / B, B>>>((float4*)num, n4);
            k_fill0<<<(n4 + B - 1) / B, B>>>((float4*)den, n4);
            k_edge<<<NANG / B, B>>>(h_bnd, h_ang, eA, eA + NANG, NANG,
                                    Wb, bb, lnb_ + 32, lnb_ + 48, num, den);
            k_node<<<NB / B, B>>>(h_bnd, NB, Wb + 3 * 256, bb + 16, lnb_ + 0, lnb_ + 16, num, den);
        }
        {
            const float* Wb  = conv_W + (c * 2 + 1) * 5 * 256;
            const float* bb  = conv_b + (c * 2 + 1) * 32;
            const float* lnb_ = conv_ln + (c * 2 + 1) * 64;
            int n4 = NA * DIM / 4;
            k_fill0<<<(n4 + B - 1) / B, B>>>((float4*)num, n4);
            k_fill0<<<(n4 + B - 1) / B, B>>>((float4*)den, n4);
            k_edge<<<NB / B, B>>>(h_atm, h_bnd, eG, eG + NB, NB,
                                  Wb, bb, lnb_ + 32, lnb_ + 48, num, den);
            k_node<<<NA / B, B>>>(h_atm, NA, Wb + 3 * 256, bb + 16, lnb_ + 0, lnb_ + 16, num, den);
        }
    }

    // ---- pool + head ----
    {
        int n4 = NGRAPH * DIM / 4;
        k_fill0<<<(n4 + B - 1) / B, B>>>((float4*)pool, n4);
    }
    k_pool<<<NA / B, B>>>(batch, NA);
    k_head<<<1, 256>>>(fp, l1W, l1b, l2W, l2b, out);
}

// round 9
// speedup vs baseline: 1.1687x; 1.1687x over previous
#include <cuda_runtime.h>
#include <math.h>
#include <stdint.h>

#define DIM 16
#define NA 131072
#define NB 1048576
#define NANG 2097152
#define NGRAPH 256
#define PI_F 3.14159274101257324219f   // fl32(pi)
#define CUTOFF_F 5.0f

// ---------------- scratch (static device globals; no runtime alloc) ----------
// Invariant: g_num/g_den/g_pool are all-zero at kernel_launch entry and are
// restored to all-zero before exit (node/head passes re-zero what edge/pool
// passes dirtied). Device globals are zero-initialized at module load.
__device__ float g_h_atm[NA * DIM];
__device__ float g_h_bnd[NB * DIM];
__device__ float g_h_ang[NANG * DIM];
__device__ float g_num[NB * DIM];
__device__ float g_den[NB * DIM];
__device__ float g_table[10 * DIM];
__device__ float g_pool[NGRAPH * DIM];
__device__ int   g_mask_mode;   // 1 = mask serialized as int32, 0 = as bytes

// ---------------- fast activations (large accuracy headroom: 3e-6 vs 1e-3) ----
__device__ __forceinline__ float sigmoid_f(float x) {
    return __fdividef(1.0f, 1.0f + __expf(-x));
}
__device__ __forceinline__ float silu_f(float x) { return x * sigmoid_f(x); }

// ---------------- accurate sinf (FMA Cody-Waite, 0 <= x < ~55) ----------------
__device__ __forceinline__ float sinf_cw(float x) {
    float k = rintf(__fmul_rn(x, 0.636619772367581343f));
    float r = fmaf(k, -1.57079637050628662109375f, x);
    r = fmaf(k, 4.37113900018624283e-8f, r);
    int q = ((int)k) & 3;
    float s = __fmul_rn(r, r);
    float ps = 2.75573192239859e-6f;
    ps = fmaf(ps, s, -1.98412698412698e-4f);
    ps = fmaf(ps, s, 8.33333333333333e-3f);
    ps = fmaf(ps, s, -1.66666666666667e-1f);
    float sinr = fmaf(__fmul_rn(r, s), ps, r);
    float pc = 2.48015873015873e-5f;
    pc = fmaf(pc, s, -1.38888888888889e-3f);
    pc = fmaf(pc, s, 4.16666666666667e-2f);
    pc = fmaf(pc, s, -5.0e-1f);
    float cosr = fmaf(s, pc, 1.0f);
    float v = (q & 1) ? cosr : sinr;
    return (q & 2) ? -v : v;
}

// ---------------- misc helpers -------------------------------------------------
__device__ __forceinline__ void red_add_v4(float* p, float a, float b, float c, float d) {
    asm volatile("red.global.add.v4.f32 [%0], {%1,%2,%3,%4};"
                 :: "l"(p), "f"(a), "f"(b), "f"(c), "f"(d) : "memory");
}
__device__ __forceinline__ void load16(float* r, const float* p) {
#pragma unroll
    for (int i = 0; i < 4; i++) {
        float4 v = ((const float4*)p)[i];
        r[4 * i + 0] = v.x; r[4 * i + 1] = v.y; r[4 * i + 2] = v.z; r[4 * i + 3] = v.w;
    }
}
__device__ __forceinline__ void load16_cs(float* r, const float* p) {
#pragma unroll
    for (int i = 0; i < 4; i++) {
        float4 v = __ldcs((const float4*)p + i);
        r[4 * i + 0] = v.x; r[4 * i + 1] = v.y; r[4 * i + 2] = v.z; r[4 * i + 3] = v.w;
    }
}
__device__ __forceinline__ void store16(float* p, const float* r) {
#pragma unroll
    for (int i = 0; i < 4; i++)
        ((float4*)p)[i] = make_float4(r[4 * i + 0], r[4 * i + 1], r[4 * i + 2], r[4 * i + 3]);
}
__device__ __forceinline__ void store16_cs(float* p, const float* r) {
#pragma unroll
    for (int i = 0; i < 4; i++)
        __stcs((float4*)p + i, make_float4(r[4 * i + 0], r[4 * i + 1], r[4 * i + 2], r[4 * i + 3]));
}

__device__ __forceinline__ void layernorm16(float* v, const float* g, const float* b) {
    float mu = 0.f;
#pragma unroll
    for (int j = 0; j < DIM; j++) mu += v[j];
    mu *= 0.0625f;
    float var = 0.f;
#pragma unroll
    for (int j = 0; j < DIM; j++) { float d0 = v[j] - mu; var = fmaf(d0, d0, var); }
    var *= 0.0625f;
    float r = __frsqrt_rn(var + 1e-5f);
#pragma unroll
    for (int j = 0; j < DIM; j++) v[j] = fmaf((v[j] - mu) * r, g[j], b[j]);
}

// ---------------- mask-layout detection ----------------------------------------
__global__ void k_detect_mask(const unsigned char* __restrict__ m) {
    __shared__ int s_nz;
    if (threadIdx.x == 0) s_nz = 0;
    __syncthreads();
    int nz = 0;
    for (int i = threadIdx.x; i < 65536; i += blockDim.x)
        if ((i & 3) && m[i]) nz = 1;
    if (nz) atomicOr(&s_nz, 1);
    __syncthreads();
    if (threadIdx.x == 0) g_mask_mode = s_nz ? 0 : 1;
}

// ---------------- atom species embedding table --------------------------------
__global__ void k_atm_table(const float* __restrict__ W1, const float* __restrict__ b1,
                            const float* __restrict__ W2, const float* __restrict__ b2,
                            const float* __restrict__ lg, const float* __restrict__ lb) {
    int s = threadIdx.x;
    if (s >= 10) return;
    float h[DIM], o[DIM];
#pragma unroll
    for (int d = 0; d < DIM; d++) h[d] = silu_f(W1[s * DIM + d] + b1[d]);
#pragma unroll
    for (int j = 0; j < DIM; j++) o[j] = b2[j];
#pragma unroll
    for (int k = 0; k < DIM; k++) {
        float a = h[k];
#pragma unroll
        for (int j = 0; j < DIM; j++) o[j] = fmaf(a, W2[k * DIM + j], o[j]);
    }
    float g[DIM], bb[DIM];
#pragma unroll
    for (int j = 0; j < DIM; j++) { g[j] = lg[j]; bb[j] = lb[j]; }
    layernorm16(o, g, bb);
#pragma unroll
    for (int j = 0; j < DIM; j++) g_table[s * DIM + j] = o[j];
}

__global__ void k_atm_gather(const int* __restrict__ species, int n) {
    int i = blockIdx.x * blockDim.x + threadIdx.x;
    if (i >= n) return;
    int s = species[i];
    const float4* src = (const float4*)(g_table + s * DIM);
    float4* dst = (float4*)(g_h_atm + (size_t)i * DIM);
#pragma unroll
    for (int q = 0; q < 4; q++) dst[q] = src[q];
}

// ---------------- generic embed ------------------------------------------------
__device__ __forceinline__ void embed_write(const float* feat, float* out,
                                            const float* sW1, const float* sb1,
                                            const float* sW2, const float* sb2,
                                            const float* sg, const float* sb) {
    float h[DIM], o[DIM];
#pragma unroll
    for (int j = 0; j < DIM; j++) h[j] = sb1[j];
#pragma unroll
    for (int k = 0; k < DIM; k++) {
        float a = feat[k];
#pragma unroll
        for (int j = 0; j < DIM; j++) h[j] = fmaf(a, sW1[k * DIM + j], h[j]);
    }
#pragma unroll
    for (int j = 0; j < DIM; j++) h[j] = silu_f(h[j]);
#pragma unroll
    for (int j = 0; j < DIM; j++) o[j] = sb2[j];
#pragma unroll
    for (int k = 0; k < DIM; k++) {
        float a = h[k];
#pragma unroll
        for (int j = 0; j < DIM; j++) o[j] = fmaf(a, sW2[k * DIM + j], o[j]);
    }
    layernorm16(o, sg, sb);
#pragma unroll
    for (int j = 0; j < DIM; j++) out[j] = o[j];
}

// ---------------- bond encoder (bessel basis) ----------------------------------
__global__ void k_enc_bnd(const float* __restrict__ xb, int n,
                          const float* __restrict__ W1, const float* __restrict__ b1,
                          const float* __restrict__ W2, const float* __restrict__ b2,
                          const float* __restrict__ lg, const float* __restrict__ lb) {
    __shared__ float sW1[256], sW2[256], sb1[16], sb2[16], sg[16], sb[16];
    int t = threadIdx.x;
    for (int i = t; i < 256; i += blockDim.x) { sW1[i] = W1[i]; sW2[i] = W2[i]; }
    if (t < 16) { sb1[t] = b1[t]; sb2[t] = b2[t]; sg[t] = lg[t]; sb[t] = lb[t]; }
    __syncthreads();
    int i = blockIdx.x * blockDim.x + t;
    if (i >= n) return;
    float xx = xb[i] + 1e-5f;
    float c0 = __fdividef(0.6324555320336759f, xx);
    float feat[DIM];
#pragma unroll
    for (int j = 0; j < DIM; j++) {
        float arg = __fmul_rn(__fmul_rn((float)(j + 1), PI_F), xx) * 0.2f;
        feat[j] = c0 * sinf_cw(arg);
    }
    float out[DIM];
    embed_write(feat, out, sW1, sb1, sW2, sb2, sg, sb);
    store16_cs(g_h_bnd + (size_t)i * DIM, out);
}

// ---------------- angle encoder (gaussian basis, dual mask layout) -------------
__global__ void k_enc_ang(const float* __restrict__ xa, const unsigned char* __restrict__ mask, int n,
                          const float* __restrict__ encW1, const float* __restrict__ encb1,
                          const float* __restrict__ encW2, const float* __restrict__ encb2,
                          const float* __restrict__ encg, const float* __restrict__ encb) {
    __shared__ float sW1[2][256], sW2[2][256], sb1[2][16], sb2[2][16], sg[2][16], sb[2][16];
    int t = threadIdx.x;
    for (int i = t; i < 512; i += blockDim.x) {
        int m = i / 256, j = i % 256;
        sW1[m][j] = encW1[(2 + m) * 256 + j];
        sW2[m][j] = encW2[(2 + m) * 256 + j];
    }
    if (t < 32) {
        int m = t / 16, j = t % 16;
        sb1[m][j] = encb1[(2 + m) * 16 + j];
        sb2[m][j] = encb2[(2 + m) * 16 + j];
        sg[m][j]  = encg[(2 + m) * 16 + j];
        sb[m][j]  = encb[(2 + m) * 16 + j];
    }
    __syncthreads();
    int i = blockIdx.x * blockDim.x + t;
    if (i >= n) return;
    int mv = g_mask_mode ? ((const int*)mask)[i] : (int)mask[i];
    int m = mv ? 1 : 0;
    float x = xa[i];
    float start = m ? -PI_F : 0.0f;
    float span  = m ? __fmul_rn(2.0f, PI_F) : PI_F;
    float step  = __fdividef(span, 15.0f);
    float gamma = __fdividef(1.0f, step);
    float feat[DIM];
#pragma unroll
    for (int j = 0; j < DIM; j++) {
        float cj = start + (float)j * step;
        float u  = gamma * (x - cj);
        feat[j] = __expf(-(u * u));
    }
    float out[DIM];
    embed_write(feat, out, sW1[m], sb1[m], sW2[m], sb2[m], sg[m], sb[m]);
    store16_cs(g_h_ang + (size_t)i * DIM, out);
}

// ---------------- edge-gated conv: edge pass -----------------------------------
template <bool STREAM_E>
__global__ void k_edge(const float* __restrict__ x, float* __restrict__ e,
                       const int* __restrict__ src, const int* __restrict__ dst, int n_edges,
                       const float* __restrict__ Wall, const float* __restrict__ bvec,
                       const float* __restrict__ lng, const float* __restrict__ lnb,
                       float* __restrict__ num, float* __restrict__ den) {
    __shared__ float sW0[256], sW1[256], sW2[256], sW4[256], sb0[16], sg[16], sb[16];
    int t = threadIdx.x;
    for (int i = t; i < 256; i += blockDim.x) {
        sW0[i] = Wall[i];
        sW1[i] = Wall[256 + i];
        sW2[i] = Wall[512 + i];
        sW4[i] = Wall[1024 + i];
    }
    if (t < 16) { sb0[t] = bvec[t]; sg[t] = lng[t]; sb[t] = lnb[t]; }
    __syncthreads();
    int eid = blockIdx.x * blockDim.x + t;
    if (eid >= n_edges) return;
    int s = src[eid], d = dst[eid];
    float xs[DIM], xd[DIM], ev[DIM];
    load16(xs, x + (size_t)s * DIM);
    load16(xd, x + (size_t)d * DIM);
    if (STREAM_E) load16_cs(ev, e + (size_t)eid * DIM);
    else          load16(ev, e + (size_t)eid * DIM);
    // msg-raw first (frees nothing but lets sig stay 4-wide)
    float msg[DIM];
#pragma unroll
    for (int j = 0; j < DIM; j++) msg[j] = 0.f;
#pragma unroll
    for (int k = 0; k < DIM; k++) {
        float a = xs[k];
#pragma unroll
        for (int j = 0; j < DIM; j++) msg[j] = fmaf(a, sW4[k * DIM + j], msg[j]);
    }
    // z = xs@W0 + xd@W1 + ev@W2 + b (single accumulator; ample numeric headroom)
    float z[DIM];
#pragma unroll
    for (int j = 0; j < DIM; j++) z[j] = sb0[j];
#pragma unroll
    for (int k = 0; k < DIM; k++) {
        float a = xs[k], b2 = xd[k], c = ev[k];
#pragma unroll
        for (int j = 0; j < DIM; j++) {
            z[j] = fmaf(a, sW0[k * DIM + j], z[j]);
            z[j] = fmaf(b2, sW1[k * DIM + j], z[j]);
            z[j] = fmaf(c, sW2[k * DIM + j], z[j]);
        }
    }
    // sigmoid in groups of 4: den atomics + msg scaling, only 4 sig live
    float* dp = den + (size_t)d * DIM;
    float* np = num + (size_t)d * DIM;
#pragma unroll
    for (int grp = 0; grp < 4; grp++) {
        float s0 = sigmoid_f(z[grp * 4 + 0]);
        float s1 = sigmoid_f(z[grp * 4 + 1]);
        float s2 = sigmoid_f(z[grp * 4 + 2]);
        float s3 = sigmoid_f(z[grp * 4 + 3]);
        red_add_v4(dp + grp * 4, s0, s1, s2, s3);
        msg[grp * 4 + 0] *= s0;
        msg[grp * 4 + 1] *= s1;
        msg[grp * 4 + 2] *= s2;
        msg[grp * 4 + 3] *= s3;
        red_add_v4(np + grp * 4, msg[grp * 4 + 0], msg[grp * 4 + 1],
                                 msg[grp * 4 + 2], msg[grp * 4 + 3]);
    }
    // e_new = e + silu(LN(z))
    layernorm16(z, sg, sb);
#pragma unroll
    for (int j = 0; j < DIM; j++) ev[j] += silu_f(z[j]);
    if (STREAM_E) store16_cs(e + (size_t)eid * DIM, ev);
    else          store16(e + (size_t)eid * DIM, ev);
}

// ---------------- edge-gated conv: node pass (also re-zeroes num/den) ----------
__global__ void k_node(float* __restrict__ x, int n_nodes,
                       const float* __restrict__ W3, const float* __restrict__ b1,
                       const float* __restrict__ lng, const float* __restrict__ lnb,
                       float* __restrict__ num, float* __restrict__ den) {
    __shared__ float sW3[256], sb1[16], sg[16], sb[16];
    int t = threadIdx.x;
    for (int i = t; i < 256; i += blockDim.x) sW3[i] = W3[i];
    if (t < 16) { sb1[t] = b1[t]; sg[t] = lng[t]; sb[t] = lnb[t]; }
    __syncthreads();
    int i = blockIdx.x * blockDim.x + t;
    if (i >= n_nodes) return;
    float xv[DIM], h[DIM], nv[DIM], dv[DIM];
    load16(xv, x + (size_t)i * DIM);
    load16(nv, num + (size_t)i * DIM);
    load16(dv, den + (size_t)i * DIM);
    // restore the all-zero invariant for the next conv (replaces fill kernels)
    float zz[DIM];
#pragma unroll
    for (int j = 0; j < DIM; j++) zz[j] = 0.f;
    store16_cs(num + (size_t)i * DIM, zz);
    store16_cs(den + (size_t)i * DIM, zz);
#pragma unroll
    for (int j = 0; j < DIM; j++) h[j] = 0.f;
#pragma unroll
    for (int k = 0; k < DIM; k++) {
        float a = xv[k];
#pragma unroll
        for (int j = 0; j < DIM; j++) h[j] = fmaf(a, sW3[k * DIM + j], h[j]);
    }
#pragma unroll
    for (int j = 0; j < DIM; j++)
        h[j] = h[j] + sb1[j] + __fdividef(nv[j], dv[j] + 1e-5f);
    layernorm16(h, sg, sb);
#pragma unroll
    for (int j = 0; j < DIM; j++) xv[j] += silu_f(h[j]);
    store16(x + (size_t)i * DIM, xv);
}

// ---------------- pooling + head -----------------------------------------------
__global__ void k_pool(const int* __restrict__ batch, int n) {
    int i = blockIdx.x * blockDim.x + threadIdx.x;
    if (i >= n) return;
    int g = batch[i];
    float h[DIM];
    load16(h, g_h_atm + (size_t)i * DIM);
    float* p = g_pool + g * DIM;
    red_add_v4(p + 0, h[0], h[1], h[2], h[3]);
    red_add_v4(p + 4, h[4], h[5], h[6], h[7]);
    red_add_v4(p + 8, h[8], h[9], h[10], h[11]);
    red_add_v4(p + 12, h[12], h[13], h[14], h[15]);
}

__global__ void k_head(const float* __restrict__ fp,
                       const float* __restrict__ l1W, const float* __restrict__ l1b,
                       const float* __restrict__ l2W, const float* __restrict__ l2b,
                       float* __restrict__ out) {
    __shared__ float sW[288], sb1h[16], sW2h[16];
    int t = threadIdx.x;
    for (int i = t; i < 288; i += blockDim.x) sW[i] = l1W[i];
    if (t < 16) { sb1h[t] = l1b[t]; sW2h[t] = l2W[t]; }
    __syncthreads();
    int g = t;  // blockDim = 256 = NGRAPH
    float xin[18];
#pragma unroll
    for (int j = 0; j < DIM; j++) xin[j] = g_pool[g * DIM + j];
    xin[16] = fp[2 * g];
    xin[17] = fp[2 * g + 1];
    // restore pool's all-zero invariant for the next call
    float zz[DIM];
#pragma unroll
    for (int j = 0; j < DIM; j++) zz[j] = 0.f;
    store16(g_pool + g * DIM, zz);
    float acc = 0.f;
#pragma unroll
    for (int d = 0; d < DIM; d++) {
        float tv = 0.f;
#pragma unroll
        for (int j = 0; j < 18; j++) tv = fmaf(xin[j], sW[j * DIM + d], tv);
        tv += sb1h[d];
        tv = (tv >= 0.f) ? tv : 0.01f * tv;
        acc = fmaf(tv, sW2h[d], acc);
    }
    out[g] = acc + l2b[0];
}

// ---------------- host ----------------------------------------------------------
extern "C" void kernel_launch(void* const* d_in, const int* in_sizes, int n_in,
                              void* d_out, int out_size) {
    const int* x_atm            = (const int*)d_in[0];
    const float* x_bnd          = (const float*)d_in[1];
    const float* x_ang          = (const float*)d_in[2];
    const unsigned char* mask   = (const unsigned char*)d_in[3];
    const int* eG               = (const int*)d_in[4];
    const int* eA               = (const int*)d_in[5];
    const int* batch            = (const int*)d_in[6];
    const float* fp             = (const float*)d_in[7];
    const float* enc_W1         = (const float*)d_in[8];
    const float* enc_b1         = (const float*)d_in[9];
    const float* enc_W2         = (const float*)d_in[10];
    const float* enc_b2         = (const float*)d_in[11];
    const float* enc_g          = (const float*)d_in[12];
    const float* enc_bb         = (const float*)d_in[13];
    const float* conv_W         = (const float*)d_in[14];
    const float* conv_b         = (const float*)d_in[15];
    const float* conv_ln        = (const float*)d_in[16];
    const float* l1W            = (const float*)d_in[17];
    const float* l1b            = (const float*)d_in[18];
    const float* l2W            = (const float*)d_in[19];
    const float* l2b            = (const float*)d_in[20];
    float* out = (float*)d_out;

    float *h_atm, *h_bnd, *h_ang, *num, *den;
    cudaGetSymbolAddress((void**)&h_atm, g_h_atm);
    cudaGetSymbolAddress((void**)&h_bnd, g_h_bnd);
    cudaGetSymbolAddress((void**)&h_ang, g_h_ang);
    cudaGetSymbolAddress((void**)&num, g_num);
    cudaGetSymbolAddress((void**)&den, g_den);

    const int B = 256;

    // ---- encoder ----
    k_detect_mask<<<1, 256>>>(mask);
    k_atm_table<<<1, 32>>>(enc_W1, enc_b1, enc_W2, enc_b2, enc_g, enc_bb);
    k_atm_gather<<<NA / B, B>>>(x_atm, NA);
    k_enc_bnd<<<NB / B, B>>>(x_bnd, NB, enc_W1 + 256, enc_b1 + 16, enc_W2 + 256,
                             enc_b2 + 16, enc_g + 16, enc_bb + 16);
    k_enc_ang<<<NANG / B, B>>>(x_ang, mask, NANG, enc_W1, enc_b1, enc_W2, enc_b2, enc_g, enc_bb);

    // ---- processor: 3 x (A conv then G conv); num/den zeroed by node passes ----
    for (int c = 0; c < 3; c++) {
        {
            const float* Wb  = conv_W + (c * 2 + 0) * 5 * 256;
            const float* bb  = conv_b + (c * 2 + 0) * 32;
            const float* lnb_ = conv_ln + (c * 2 + 0) * 64;
            k_edge<true><<<NANG / B, B>>>(h_bnd, h_ang, eA, eA + NANG, NANG,
                                          Wb, bb, lnb_ + 32, lnb_ + 48, num, den);
            k_node<<<NB / B, B>>>(h_bnd, NB, Wb + 3 * 256, bb + 16, lnb_ + 0, lnb_ + 16, num, den);
        }
        {
            const float* Wb  = conv_W + (c * 2 + 1) * 5 * 256;
            const float* bb  = conv_b + (c * 2 + 1) * 32;
            const float* lnb_ = conv_ln + (c * 2 + 1) * 64;
            k_edge<false><<<NB / B, B>>>(h_atm, h_bnd, eG, eG + NB, NB,
                                         Wb, bb, lnb_ + 32, lnb_ + 48, num, den);
            k_node<<<NA / B, B>>>(h_atm, NA, Wb + 3 * 256, bb + 16, lnb_ + 0, lnb_ + 16, num, den);
        }
    }

    // ---- pool + head (pool zeroed by head) ----
    k_pool<<<NA / B, B>>>(batch, NA);
    k_head<<<1, 256>>>(fp, l1W, l1b, l2W, l2b, out);
}